// round 6
// baseline (speedup 1.0000x reference)
#include <cuda_runtime.h>
#include <cuda_bf16.h>

#define BATCH 2
#define CIN   256
#define CR    64
#define HH    64
#define WW    64
#define NPIX  4096

#define FFMA2(d, a, b) asm("fma.rn.f32x2 %0, %1, %2, %0;" : "+l"(d) : "l"(a), "l"(b))
#define PACK2(d, lo, hi) asm("mov.b64 %0, {%1, %2};" : "=l"(d) : "f"(lo), "f"(hi))
#define CP_ASYNC16(dst, src) asm volatile("cp.async.cg.shared.global [%0], [%1], 16;" :: "r"(dst), "l"(src))
#define CP_COMMIT()  asm volatile("cp.async.commit_group;")
#define CP_WAIT0()   asm volatile("cp.async.wait_group 0;")

union F2U { unsigned long long u; float2 f; };

// device scratch
__device__ float  g_e  [BATCH * CR * NPIX];        // e fp32 [b][k][n]
__device__ unsigned g_ebf[BATCH * CR * NPIX / 2];  // e bf16x2 [b][k][n/2]
__device__ float  g_et [BATCH * NPIX * CR];        // e fp32 transposed [b][n][k]
__device__ float2 g_wt2[CIN * 9 * CR];             // dup-packed weights
__device__ float  g_part[4 * BATCH * CR * NPIX];   // conv partials
__device__ float  g_xt [BATCH * NPIX * CIN];       // x transposed [b][n][c]
__device__ __nv_bfloat16 g_sim[(size_t)BATCH * NPIX * NPIX];  // sim bf16 [b][n][m]

// GEMM smem: B panel 64x1024 bf16 (128KB) + A panel 64x32 dup float2 (16KB)
#define GEMM_SMEM (64 * 1024 * 2 + 64 * 32 * 8)

// ---------------------------------------------------------------------------
// out = x  AND  g_xt[b][n][c] = x[b][c][n]
// ---------------------------------------------------------------------------
__global__ __launch_bounds__(256) void init_transpose_kernel(
    const float* __restrict__ x, float* __restrict__ out)
{
    __shared__ float s[32][33];
    const int b  = blockIdx.z;
    const int n0 = blockIdx.x * 32;
    const int c0 = blockIdx.y * 32;
    const int tx = threadIdx.x, ty = threadIdx.y;
    #pragma unroll
    for (int j = 0; j < 4; j++) {
        int c = c0 + ty + j * 8;
        float v = x[(b * CIN + c) * NPIX + n0 + tx];
        out[(b * CIN + c) * NPIX + n0 + tx] = v;
        s[ty + j * 8][tx] = v;
    }
    __syncthreads();
    #pragma unroll
    for (int j = 0; j < 4; j++) {
        int n = n0 + ty + j * 8;
        g_xt[(b * NPIX + n) * CIN + c0 + tx] = s[tx][ty + j * 8];
    }
}

__global__ void wt_transpose_kernel(const float* __restrict__ w) {
    int i = blockIdx.x * blockDim.x + threadIdx.x;
    if (i < CR * CIN * 9) {
        int co = i / (CIN * 9);
        int q  = i % (CIN * 9);
        float v = w[i];
        g_wt2[q * CR + co] = make_float2(v, v);
    }
}

// ---------------------------------------------------------------------------
// conv3x3 partial (ci-split x4), f32x2
// ---------------------------------------------------------------------------
__global__ __launch_bounds__(256) void conv_partial_kernel(const float* __restrict__ x)
{
    __shared__ __align__(16) float  s_x[8][3][68];
    __shared__ __align__(16) float2 s_w[8][9][64];

    const int h   = blockIdx.x;
    const int cis = blockIdx.y;
    const int b   = blockIdx.z;
    const int cib = cis * 64;
    const int t   = threadIdx.x;
    const int cg  = t >> 4;
    const int px0 = (t & 15) * 4;

    unsigned long long acc[4][2];
    #pragma unroll
    for (int j = 0; j < 4; j++) { acc[j][0] = 0ull; acc[j][1] = 0ull; }

    for (int ci0 = cib; ci0 < cib + 64; ci0 += 8) {
        __syncthreads();
        for (int idx = t; idx < 8 * 3 * 66; idx += 256) {
            int ci = idx / 198;
            int rem = idx % 198;
            int r  = rem / 66;
            int c2 = rem % 66;
            int hh = h - 1 + r;
            int cc = c2 - 1;
            float v = 0.f;
            if (hh >= 0 && hh < HH && cc >= 0 && cc < WW)
                v = x[((b * CIN + ci0 + ci) * HH + hh) * WW + cc];
            s_x[ci][r][c2] = v;
        }
        for (int idx = t; idx < 8 * 9 * 64; idx += 256) {
            int ci = idx / 576;
            int rem = idx % 576;
            int kk = rem >> 6;
            int co = rem & 63;
            s_w[ci][kk][co] = g_wt2[((ci0 + ci) * 9 + kk) * CR + co];
        }
        __syncthreads();

        #pragma unroll
        for (int ci = 0; ci < 8; ci++) {
            #pragma unroll
            for (int kh = 0; kh < 3; kh++) {
                float4 xa  = *(const float4*)&s_x[ci][kh][px0];
                float2 xb2 = *(const float2*)&s_x[ci][kh][px0 + 4];
                float xv[6] = {xa.x, xa.y, xa.z, xa.w, xb2.x, xb2.y};
                #pragma unroll
                for (int kw = 0; kw < 3; kw++) {
                    unsigned long long xp0, xp1;
                    PACK2(xp0, xv[kw],     xv[kw + 1]);
                    PACK2(xp1, xv[kw + 2], xv[kw + 3]);
                    ulonglong2 w01 = *(const ulonglong2*)&s_w[ci][kh * 3 + kw][cg * 4];
                    ulonglong2 w23 = *(const ulonglong2*)&s_w[ci][kh * 3 + kw][cg * 4 + 2];
                    FFMA2(acc[0][0], w01.x, xp0);  FFMA2(acc[0][1], w01.x, xp1);
                    FFMA2(acc[1][0], w01.y, xp0);  FFMA2(acc[1][1], w01.y, xp1);
                    FFMA2(acc[2][0], w23.x, xp0);  FFMA2(acc[2][1], w23.x, xp1);
                    FFMA2(acc[3][0], w23.y, xp0);  FFMA2(acc[3][1], w23.y, xp1);
                }
            }
        }
    }

    float* dst = g_part + ((cis * BATCH + b) * CR) * NPIX;
    #pragma unroll
    for (int j = 0; j < 4; j++) {
        F2U u0, u1; u0.u = acc[j][0]; u1.u = acc[j][1];
        float4 v = make_float4(u0.f.x, u0.f.y, u1.f.x, u1.f.y);
        int co = cg * 4 + j;
        *(float4*)&dst[co * NPIX + h * WW + px0] = v;
    }
}

// ---------------------------------------------------------------------------
// epilogue: sum partials + bias + BN + PReLU -> g_e (fp32), g_ebf (bf16),
//           g_et (fp32 transposed)
// ---------------------------------------------------------------------------
__global__ __launch_bounds__(256) void conv_epilogue_kernel(
    const float* __restrict__ cb, const float* __restrict__ gamma,
    const float* __restrict__ beta, const float* __restrict__ mean,
    const float* __restrict__ var, const float* __restrict__ prelu)
{
    const int i = blockIdx.x * blockDim.x + threadIdx.x;
    const int per_b4 = CR * NPIX / 4;
    if (i >= BATCH * per_b4) return;
    const int b   = i / per_b4;
    const int rem = i % per_b4;
    const int co  = rem / (NPIX / 4);
    const int n4  = rem % (NPIX / 4);

    float4 v0 = ((const float4*)g_part)[(0 * BATCH + b) * per_b4 + rem];
    float4 v1 = ((const float4*)g_part)[(1 * BATCH + b) * per_b4 + rem];
    float4 v2 = ((const float4*)g_part)[(2 * BATCH + b) * per_b4 + rem];
    float4 v3 = ((const float4*)g_part)[(3 * BATCH + b) * per_b4 + rem];
    float4 s;
    s.x = (v0.x + v1.x) + (v2.x + v3.x);
    s.y = (v0.y + v1.y) + (v2.y + v3.y);
    s.z = (v0.z + v1.z) + (v2.z + v3.z);
    s.w = (v0.w + v1.w) + (v2.w + v3.w);

    const float sc    = gamma[co] * rsqrtf(var[co] + 1e-5f);
    const float base  = (cb[co] - mean[co]) * sc + beta[co];
    const float slope = prelu[0];
    float y;
    y = s.x * sc + base; s.x = (y >= 0.f) ? y : slope * y;
    y = s.y * sc + base; s.y = (y >= 0.f) ? y : slope * y;
    y = s.z * sc + base; s.z = (y >= 0.f) ? y : slope * y;
    y = s.w * sc + base; s.w = (y >= 0.f) ? y : slope * y;

    ((float4*)g_e)[b * per_b4 + rem] = s;

    unsigned q0, q1;
    asm("cvt.rn.bf16x2.f32 %0, %1, %2;" : "=r"(q0) : "f"(s.y), "f"(s.x));
    asm("cvt.rn.bf16x2.f32 %0, %1, %2;" : "=r"(q1) : "f"(s.w), "f"(s.z));
    ((uint2*)g_ebf)[b * per_b4 + rem] = make_uint2(q0, q1);

    const int nb = n4 * 4;
    float* et = g_et + (b * NPIX + nb) * CR + co;
    et[0 * CR] = s.x;
    et[1 * CR] = s.y;
    et[2 * CR] = s.z;
    et[3 * CR] = s.w;
}

// ---------------------------------------------------------------------------
// GEMM: sim_bf[b][n0..n0+31][m0..m0+1023] = e(fp32)^T . e(bf16)
// B panel loaded once (128KB smem). acc 8x8 per thread via f32x2.
// ---------------------------------------------------------------------------
__global__ __launch_bounds__(512) void gemm_sim_kernel()
{
    extern __shared__ __align__(16) char smem_raw[];
    char*   s_B8  = smem_raw;                         // 64 x 1024 bf16
    float2* s_A2  = (float2*)(smem_raw + 64 * 1024 * 2);  // 64 x 32 dup pairs

    const int b  = blockIdx.z;
    const int n0 = blockIdx.y * 32;
    const int m0 = blockIdx.x * 1024;
    const int t  = threadIdx.x;

    // A panel: fp32, dup-packed
    #pragma unroll
    for (int j = 0; j < 4; j++) {
        int idx = t * 4 + j;              // 0..2047
        int k = idx >> 5, r = idx & 31;
        float v = g_e[(b * CR + k) * NPIX + n0 + r];
        s_A2[k * 32 + r] = make_float2(v, v);
    }

    // B panel: bf16, cp.async 128KB
    {
        unsigned sB = (unsigned)__cvta_generic_to_shared(s_B8);
        const char* src_base = (const char*)g_ebf + ((size_t)b * CR * NPIX + m0) * 2;
        #pragma unroll
        for (int j = 0; j < 16; j++) {
            int gidx = t + j * 512;        // 0..8191
            int k  = gidx >> 7;            // row
            int ch = gidx & 127;           // 16B chunk in row
            CP_ASYNC16(sB + (unsigned)(k * 2048 + ch * 16),
                       src_base + (size_t)k * NPIX * 2 + ch * 16);
        }
        CP_COMMIT();
        CP_WAIT0();
    }
    __syncthreads();

    const int rg = t >> 7;          // 0..3  -> rows rg*8..+7
    const int c0 = (t & 127) * 8;   // 8 cols

    unsigned long long acc[8][4];
    #pragma unroll
    for (int r = 0; r < 8; r++)
        #pragma unroll
        for (int cp = 0; cp < 4; cp++) acc[r][cp] = 0ull;

    #pragma unroll 4
    for (int k = 0; k < CR; k++) {
        const ulonglong2* Ap = (const ulonglong2*)(s_A2 + k * 32 + rg * 8);
        ulonglong2 a01 = Ap[0], a23 = Ap[1], a45 = Ap[2], a67 = Ap[3];

        uint4 braw = *(const uint4*)(s_B8 + k * 2048 + c0 * 2);
        unsigned long long b0, b1, b2, b3;
        PACK2(b0, __uint_as_float(braw.x << 16), __uint_as_float(braw.x & 0xffff0000u));
        PACK2(b1, __uint_as_float(braw.y << 16), __uint_as_float(braw.y & 0xffff0000u));
        PACK2(b2, __uint_as_float(braw.z << 16), __uint_as_float(braw.z & 0xffff0000u));
        PACK2(b3, __uint_as_float(braw.w << 16), __uint_as_float(braw.w & 0xffff0000u));

        FFMA2(acc[0][0], a01.x, b0); FFMA2(acc[0][1], a01.x, b1);
        FFMA2(acc[0][2], a01.x, b2); FFMA2(acc[0][3], a01.x, b3);
        FFMA2(acc[1][0], a01.y, b0); FFMA2(acc[1][1], a01.y, b1);
        FFMA2(acc[1][2], a01.y, b2); FFMA2(acc[1][3], a01.y, b3);
        FFMA2(acc[2][0], a23.x, b0); FFMA2(acc[2][1], a23.x, b1);
        FFMA2(acc[2][2], a23.x, b2); FFMA2(acc[2][3], a23.x, b3);
        FFMA2(acc[3][0], a23.y, b0); FFMA2(acc[3][1], a23.y, b1);
        FFMA2(acc[3][2], a23.y, b2); FFMA2(acc[3][3], a23.y, b3);
        FFMA2(acc[4][0], a45.x, b0); FFMA2(acc[4][1], a45.x, b1);
        FFMA2(acc[4][2], a45.x, b2); FFMA2(acc[4][3], a45.x, b3);
        FFMA2(acc[5][0], a45.y, b0); FFMA2(acc[5][1], a45.y, b1);
        FFMA2(acc[5][2], a45.y, b2); FFMA2(acc[5][3], a45.y, b3);
        FFMA2(acc[6][0], a67.x, b0); FFMA2(acc[6][1], a67.x, b1);
        FFMA2(acc[6][2], a67.x, b2); FFMA2(acc[6][3], a67.x, b3);
        FFMA2(acc[7][0], a67.y, b0); FFMA2(acc[7][1], a67.y, b1);
        FFMA2(acc[7][2], a67.y, b2); FFMA2(acc[7][3], a67.y, b3);
    }

    // write bf16 sim
    #pragma unroll
    for (int r = 0; r < 8; r++) {
        int row = n0 + rg * 8 + r;
        uint4 q;
        F2U u;
        u.u = acc[r][0];
        asm("cvt.rn.bf16x2.f32 %0, %1, %2;" : "=r"(q.x) : "f"(u.f.y), "f"(u.f.x));
        u.u = acc[r][1];
        asm("cvt.rn.bf16x2.f32 %0, %1, %2;" : "=r"(q.y) : "f"(u.f.y), "f"(u.f.x));
        u.u = acc[r][2];
        asm("cvt.rn.bf16x2.f32 %0, %1, %2;" : "=r"(q.z) : "f"(u.f.y), "f"(u.f.x));
        u.u = acc[r][3];
        asm("cvt.rn.bf16x2.f32 %0, %1, %2;" : "=r"(q.w) : "f"(u.f.y), "f"(u.f.x));
        *(uint4*)((char*)g_sim + ((size_t)(b * NPIX + row) * NPIX + m0 + c0) * 2) = q;
    }
}

// ---------------------------------------------------------------------------
// Row kernel (256 thr): bf16 max, ballot-compacted candidates (> M - 3),
// exact fp32 rescue (8 warps), Michelot, positive-compacted scatter.
// ---------------------------------------------------------------------------
__global__ __launch_bounds__(256) void sparsemax_row_kernel(float* __restrict__ out)
{
    __shared__ __align__(16) unsigned s_row[NPIX / 2];   // 8KB
    __shared__ int   s_idx[NPIX];                        // 16KB
    __shared__ float s_val[NPIX];                        // 16KB
    __shared__ float s_rf[8];
    __shared__ int   s_ri[8];
    __shared__ float s_Mbf, s_Mex;
    __shared__ int   s_c, s_pk;
    __shared__ int   s_pidx[512];
    __shared__ float s_pv[512];

    const int n    = blockIdx.x;
    const int b    = blockIdx.y;
    const int t    = threadIdx.x;
    const int wid  = t >> 5;
    const int lane = t & 31;

    if (t == 0) { s_c = 0; s_pk = 0; }

    // load row + running max
    float m = -3.0e38f;
    {
        const uint4* rp = (const uint4*)((const char*)g_sim + (size_t)(b * NPIX + n) * NPIX * 2);
        #pragma unroll
        for (int j = 0; j < 2; j++) {
            int idx = t + j * 256;
            uint4 u = rp[idx];
            ((uint4*)s_row)[idx] = u;
            m = fmaxf(m, fmaxf(__uint_as_float(u.x << 16), __uint_as_float(u.x & 0xffff0000u)));
            m = fmaxf(m, fmaxf(__uint_as_float(u.y << 16), __uint_as_float(u.y & 0xffff0000u)));
            m = fmaxf(m, fmaxf(__uint_as_float(u.z << 16), __uint_as_float(u.z & 0xffff0000u)));
            m = fmaxf(m, fmaxf(__uint_as_float(u.w << 16), __uint_as_float(u.w & 0xffff0000u)));
        }
    }
    #pragma unroll
    for (int o = 16; o; o >>= 1) m = fmaxf(m, __shfl_xor_sync(0xffffffffu, m, o));
    if (lane == 0) s_rf[wid] = m;
    __syncthreads();
    if (t == 0) {
        float mm = s_rf[0];
        #pragma unroll
        for (int w = 1; w < 8; w++) mm = fmaxf(mm, s_rf[w]);
        s_Mbf = mm;
    }
    __syncthreads();

    const float th = s_Mbf - 3.0f;
    const unsigned lt_mask = (1u << lane) - 1u;

    // warp-aggregated candidate compaction
    #pragma unroll
    for (int j = 0; j < 8; j++) {
        int i = t + j * 256;
        unsigned u = s_row[i];
        float v0 = __uint_as_float(u << 16);
        float v1 = __uint_as_float(u & 0xffff0000u);
        bool c0 = v0 > th, c1 = v1 > th;
        unsigned m0 = __ballot_sync(0xffffffffu, c0);
        unsigned m1 = __ballot_sync(0xffffffffu, c1);
        int tot = __popc(m0) + __popc(m1);
        int base = 0;
        if (lane == 0 && tot) base = atomicAdd(&s_c, tot);
        base = __shfl_sync(0xffffffffu, base, 0);
        if (c0) s_idx[base + __popc(m0 & lt_mask)] = 2 * i;
        if (c1) s_idx[base + __popc(m0) + __popc(m1 & lt_mask)] = 2 * i + 1;
    }
    __syncthreads();
    const int c = s_c;

    // exact fp32 rescue dots (warp per candidate, 8 warps)
    {
        const float2 en = *(const float2*)&g_et[(size_t)(b * NPIX + n) * CR + lane * 2];
        for (int j = wid; j < c; j += 8) {
            int mcol = s_idx[j];
            float2 em = *(const float2*)&g_et[(size_t)(b * NPIX + mcol) * CR + lane * 2];
            float sum = en.x * em.x + en.y * em.y;
            #pragma unroll
            for (int o = 16; o; o >>= 1) sum += __shfl_xor_sync(0xffffffffu, sum, o);
            if (lane == 0) s_val[j] = sum;
        }
    }
    __syncthreads();

    // exact max over candidates
    {
        float mm = -3.0e38f;
        for (int j = t; j < c; j += 256) mm = fmaxf(mm, s_val[j]);
        #pragma unroll
        for (int o = 16; o; o >>= 1) mm = fmaxf(mm, __shfl_xor_sync(0xffffffffu, mm, o));
        if (lane == 0) s_rf[wid] = mm;
        __syncthreads();
        if (t == 0) {
            float v = s_rf[0];
            #pragma unroll
            for (int w = 1; w < 8; w++) v = fmaxf(v, s_rf[w]);
            s_Mex = v;
        }
        __syncthreads();
    }
    const float Mex = s_Mex;

    // exact Michelot on candidate set
    float tau = -3.0e38f;
    int prev = -1;
    for (int it = 0; it < 64; it++) {
        float ss = 0.f; int cnt = 0;
        for (int j = t; j < c; j += 256) {
            float z = s_val[j] - Mex;
            if (z > tau) { ss += z; cnt++; }
        }
        #pragma unroll
        for (int o = 16; o; o >>= 1) {
            ss  += __shfl_xor_sync(0xffffffffu, ss, o);
            cnt += __shfl_xor_sync(0xffffffffu, cnt, o);
        }
        if (lane == 0) { s_rf[wid] = ss; s_ri[wid] = cnt; }
        __syncthreads();
        float tss = 0.f; int tcn = 0;
        #pragma unroll
        for (int w = 0; w < 8; w++) { tss += s_rf[w]; tcn += s_ri[w]; }
        __syncthreads();
        tau = (tss - 1.f) / (float)tcn;
        if (tcn == prev) break;
        prev = tcn;
    }

    // positive-support compaction (ballot-aggregated), then scatter
    for (int j0 = 0; j0 < c; j0 += 256) {
        int j = j0 + t;
        float p = 0.f;
        bool pos = false;
        if (j < c) {
            p = s_val[j] - Mex - tau;
            pos = p > 0.f;
        }
        unsigned mk = __ballot_sync(0xffffffffu, pos);
        int base = 0;
        if (lane == 0 && mk) base = atomicAdd(&s_pk, __popc(mk));
        base = __shfl_sync(0xffffffffu, base, 0);
        if (pos) {
            int pos_i = base + __popc(mk & lt_mask);
            if (pos_i < 512) { s_pidx[pos_i] = s_idx[j]; s_pv[pos_i] = p; }
        }
    }
    __syncthreads();

    const float xv = g_xt[(size_t)(b * NPIX + n) * CIN + t];
    float* ob = out + (size_t)b * CIN * NPIX;
    const int kp = s_pk < 512 ? s_pk : 512;
    for (int jj = 0; jj < kp; jj++)
        atomicAdd(&ob[(size_t)t * NPIX + s_pidx[jj]], s_pv[jj] * xv);

    // overflow fallback (support > 512): scan remaining candidates directly
    if (s_pk > 512) {
        for (int j = 0; j < c; j++) {
            float p = s_val[j] - Mex - tau;
            if (p > 0.f) {
                // skip entries already handled via compacted list
                bool done = false;
                for (int q = 0; q < kp; q++) if (s_pidx[q] == s_idx[j]) { done = true; break; }
                if (!done)
                    atomicAdd(&ob[(size_t)t * NPIX + s_idx[j]], p * xv);
            }
        }
    }
}

// ---------------------------------------------------------------------------
extern "C" void kernel_launch(void* const* d_in, const int* in_sizes, int n_in,
                              void* d_out, int out_size)
{
    const float* x      = (const float*)d_in[0];
    const float* conv_w = (const float*)d_in[1];
    const float* conv_b = (const float*)d_in[2];
    const float* gamma  = (const float*)d_in[3];
    const float* beta   = (const float*)d_in[4];
    const float* mean   = (const float*)d_in[5];
    const float* var    = (const float*)d_in[6];
    const float* prelu  = (const float*)d_in[7];
    float* out = (float*)d_out;

    cudaFuncSetAttribute(gemm_sim_kernel,
                         cudaFuncAttributeMaxDynamicSharedMemorySize, GEMM_SMEM);

    init_transpose_kernel<<<dim3(NPIX / 32, CIN / 32, BATCH), dim3(32, 8)>>>(x, out);

    int wtot = CR * CIN * 9;
    wt_transpose_kernel<<<(wtot + 255) / 256, 256>>>(conv_w);

    conv_partial_kernel<<<dim3(HH, 4, BATCH), 256>>>(x);

    int etot4 = BATCH * CR * NPIX / 4;
    conv_epilogue_kernel<<<(etot4 + 255) / 256, 256>>>(
        conv_b, gamma, beta, mean, var, prelu);

    gemm_sim_kernel<<<dim3(NPIX / 1024, NPIX / 32, BATCH), 512, GEMM_SMEM>>>();

    sparsemax_row_kernel<<<dim3(NPIX, BATCH), 256>>>(out);
}

// round 7
// speedup vs baseline: 1.0146x; 1.0146x over previous
#include <cuda_runtime.h>
#include <cuda_bf16.h>

#define BATCH 2
#define CIN   256
#define CR    64
#define HH    64
#define WW    64
#define NPIX  4096
#define CAP   4096          // candidate list capacity per row (= NPIX, cannot overflow)

#define FFMA2(d, a, b) asm("fma.rn.f32x2 %0, %1, %2, %0;" : "+l"(d) : "l"(a), "l"(b))
#define PACK2(d, lo, hi) asm("mov.b64 %0, {%1, %2};" : "=l"(d) : "f"(lo), "f"(hi))
#define CP_ASYNC16(dst, src) asm volatile("cp.async.cg.shared.global [%0], [%1], 16;" :: "r"(dst), "l"(src))
#define CP_COMMIT()  asm volatile("cp.async.commit_group;")
#define CP_WAIT0()   asm volatile("cp.async.wait_group 0;")

union F2U { unsigned long long u; float2 f; };

// device scratch
__device__ float  g_e  [BATCH * CR * NPIX];        // e fp32 [b][k][n]
__device__ unsigned g_ebf[BATCH * CR * NPIX / 2];  // e bf16x2 [b][k][n/2]
__device__ float  g_et [BATCH * NPIX * CR];        // e fp32 transposed [b][n][k]
__device__ float2 g_wt2[CIN * 9 * CR];             // dup-packed weights
__device__ float  g_part[4 * BATCH * CR * NPIX];   // conv partials
__device__ float  g_xt [BATCH * NPIX * CIN];       // x transposed [b][n][c]
__device__ float  g_norm[BATCH * NPIX];            // ||e_n||^2 (exact fp32)
__device__ int    g_cnt [BATCH * NPIX];            // candidate counts
__device__ int    g_cidx[(size_t)BATCH * NPIX * CAP];  // candidate column lists

// GEMM smem: B panel 64x1024 bf16 (128KB) + A panel 64x32 dup float2 (16KB)
#define GEMM_SMEM (64 * 1024 * 2 + 64 * 32 * 8)

// ---------------------------------------------------------------------------
// out = x  AND  g_xt[b][n][c] = x[b][c][n]
// ---------------------------------------------------------------------------
__global__ __launch_bounds__(256) void init_transpose_kernel(
    const float* __restrict__ x, float* __restrict__ out)
{
    __shared__ float s[32][33];
    const int b  = blockIdx.z;
    const int n0 = blockIdx.x * 32;
    const int c0 = blockIdx.y * 32;
    const int tx = threadIdx.x, ty = threadIdx.y;
    #pragma unroll
    for (int j = 0; j < 4; j++) {
        int c = c0 + ty + j * 8;
        float v = x[(b * CIN + c) * NPIX + n0 + tx];
        out[(b * CIN + c) * NPIX + n0 + tx] = v;
        s[ty + j * 8][tx] = v;
    }
    __syncthreads();
    #pragma unroll
    for (int j = 0; j < 4; j++) {
        int n = n0 + ty + j * 8;
        g_xt[(b * NPIX + n) * CIN + c0 + tx] = s[tx][ty + j * 8];
    }
}

// ---------------------------------------------------------------------------
// weight transpose + zero norm/cnt scratch
// ---------------------------------------------------------------------------
__global__ void wt_transpose_kernel(const float* __restrict__ w) {
    int i = blockIdx.x * blockDim.x + threadIdx.x;
    if (i < BATCH * NPIX) { g_cnt[i] = 0; g_norm[i] = 0.f; }
    if (i < CR * CIN * 9) {
        int co = i / (CIN * 9);
        int q  = i % (CIN * 9);
        float v = w[i];
        g_wt2[q * CR + co] = make_float2(v, v);
    }
}

// ---------------------------------------------------------------------------
// conv3x3 partial (ci-split x4), f32x2
// ---------------------------------------------------------------------------
__global__ __launch_bounds__(256) void conv_partial_kernel(const float* __restrict__ x)
{
    __shared__ __align__(16) float  s_x[8][3][68];
    __shared__ __align__(16) float2 s_w[8][9][64];

    const int h   = blockIdx.x;
    const int cis = blockIdx.y;
    const int b   = blockIdx.z;
    const int cib = cis * 64;
    const int t   = threadIdx.x;
    const int cg  = t >> 4;
    const int px0 = (t & 15) * 4;

    unsigned long long acc[4][2];
    #pragma unroll
    for (int j = 0; j < 4; j++) { acc[j][0] = 0ull; acc[j][1] = 0ull; }

    for (int ci0 = cib; ci0 < cib + 64; ci0 += 8) {
        __syncthreads();
        for (int idx = t; idx < 8 * 3 * 66; idx += 256) {
            int ci = idx / 198;
            int rem = idx % 198;
            int r  = rem / 66;
            int c2 = rem % 66;
            int hh = h - 1 + r;
            int cc = c2 - 1;
            float v = 0.f;
            if (hh >= 0 && hh < HH && cc >= 0 && cc < WW)
                v = x[((b * CIN + ci0 + ci) * HH + hh) * WW + cc];
            s_x[ci][r][c2] = v;
        }
        for (int idx = t; idx < 8 * 9 * 64; idx += 256) {
            int ci = idx / 576;
            int rem = idx % 576;
            int kk = rem >> 6;
            int co = rem & 63;
            s_w[ci][kk][co] = g_wt2[((ci0 + ci) * 9 + kk) * CR + co];
        }
        __syncthreads();

        #pragma unroll
        for (int ci = 0; ci < 8; ci++) {
            #pragma unroll
            for (int kh = 0; kh < 3; kh++) {
                float4 xa  = *(const float4*)&s_x[ci][kh][px0];
                float2 xb2 = *(const float2*)&s_x[ci][kh][px0 + 4];
                float xv[6] = {xa.x, xa.y, xa.z, xa.w, xb2.x, xb2.y};
                #pragma unroll
                for (int kw = 0; kw < 3; kw++) {
                    unsigned long long xp0, xp1;
                    PACK2(xp0, xv[kw],     xv[kw + 1]);
                    PACK2(xp1, xv[kw + 2], xv[kw + 3]);
                    ulonglong2 w01 = *(const ulonglong2*)&s_w[ci][kh * 3 + kw][cg * 4];
                    ulonglong2 w23 = *(const ulonglong2*)&s_w[ci][kh * 3 + kw][cg * 4 + 2];
                    FFMA2(acc[0][0], w01.x, xp0);  FFMA2(acc[0][1], w01.x, xp1);
                    FFMA2(acc[1][0], w01.y, xp0);  FFMA2(acc[1][1], w01.y, xp1);
                    FFMA2(acc[2][0], w23.x, xp0);  FFMA2(acc[2][1], w23.x, xp1);
                    FFMA2(acc[3][0], w23.y, xp0);  FFMA2(acc[3][1], w23.y, xp1);
                }
            }
        }
    }

    float* dst = g_part + ((cis * BATCH + b) * CR) * NPIX;
    #pragma unroll
    for (int j = 0; j < 4; j++) {
        F2U u0, u1; u0.u = acc[j][0]; u1.u = acc[j][1];
        float4 v = make_float4(u0.f.x, u0.f.y, u1.f.x, u1.f.y);
        int co = cg * 4 + j;
        *(float4*)&dst[co * NPIX + h * WW + px0] = v;
    }
}

// ---------------------------------------------------------------------------
// epilogue: sum partials + bias + BN + PReLU -> g_e, g_ebf, g_et, g_norm(atomic)
// ---------------------------------------------------------------------------
__global__ __launch_bounds__(256) void conv_epilogue_kernel(
    const float* __restrict__ cb, const float* __restrict__ gamma,
    const float* __restrict__ beta, const float* __restrict__ mean,
    const float* __restrict__ var, const float* __restrict__ prelu)
{
    const int i = blockIdx.x * blockDim.x + threadIdx.x;
    const int per_b4 = CR * NPIX / 4;
    if (i >= BATCH * per_b4) return;
    const int b   = i / per_b4;
    const int rem = i % per_b4;
    const int co  = rem / (NPIX / 4);
    const int n4  = rem % (NPIX / 4);

    float4 v0 = ((const float4*)g_part)[(0 * BATCH + b) * per_b4 + rem];
    float4 v1 = ((const float4*)g_part)[(1 * BATCH + b) * per_b4 + rem];
    float4 v2 = ((const float4*)g_part)[(2 * BATCH + b) * per_b4 + rem];
    float4 v3 = ((const float4*)g_part)[(3 * BATCH + b) * per_b4 + rem];
    float4 s;
    s.x = (v0.x + v1.x) + (v2.x + v3.x);
    s.y = (v0.y + v1.y) + (v2.y + v3.y);
    s.z = (v0.z + v1.z) + (v2.z + v3.z);
    s.w = (v0.w + v1.w) + (v2.w + v3.w);

    const float sc    = gamma[co] * rsqrtf(var[co] + 1e-5f);
    const float base  = (cb[co] - mean[co]) * sc + beta[co];
    const float slope = prelu[0];
    float y;
    y = s.x * sc + base; s.x = (y >= 0.f) ? y : slope * y;
    y = s.y * sc + base; s.y = (y >= 0.f) ? y : slope * y;
    y = s.z * sc + base; s.z = (y >= 0.f) ? y : slope * y;
    y = s.w * sc + base; s.w = (y >= 0.f) ? y : slope * y;

    ((float4*)g_e)[b * per_b4 + rem] = s;

    unsigned q0, q1;
    asm("cvt.rn.bf16x2.f32 %0, %1, %2;" : "=r"(q0) : "f"(s.y), "f"(s.x));
    asm("cvt.rn.bf16x2.f32 %0, %1, %2;" : "=r"(q1) : "f"(s.w), "f"(s.z));
    ((uint2*)g_ebf)[b * per_b4 + rem] = make_uint2(q0, q1);

    const int nb = n4 * 4;
    float* et = g_et + (b * NPIX + nb) * CR + co;
    et[0 * CR] = s.x;
    et[1 * CR] = s.y;
    et[2 * CR] = s.z;
    et[3 * CR] = s.w;

    // accumulate ||e_n||^2
    atomicAdd(&g_norm[b * NPIX + nb + 0], s.x * s.x);
    atomicAdd(&g_norm[b * NPIX + nb + 1], s.y * s.y);
    atomicAdd(&g_norm[b * NPIX + nb + 2], s.z * s.z);
    atomicAdd(&g_norm[b * NPIX + nb + 3], s.w * s.w);
}

// ---------------------------------------------------------------------------
// GEMM+filter: z[n][m] = e(fp32)^T . e(bf16) for 32 rows x 1024 cols per CTA.
// Sim is NEVER written: columns with z > norm_n - 1.4 are appended to per-row
// candidate lists (norm_n <= row max, support z > tau >= max-1; bf16 err < 0.4).
// ---------------------------------------------------------------------------
__global__ __launch_bounds__(512) void gemm_filter_kernel()
{
    extern __shared__ __align__(16) char smem_raw[];
    char*   s_B8  = smem_raw;                             // 64 x 1024 bf16
    float2* s_A2  = (float2*)(smem_raw + 64 * 1024 * 2);  // 64 x 32 dup pairs

    const int b  = blockIdx.z;
    const int n0 = blockIdx.y * 32;
    const int m0 = blockIdx.x * 1024;
    const int t  = threadIdx.x;

    // A panel: fp32, dup-packed
    #pragma unroll
    for (int j = 0; j < 4; j++) {
        int idx = t * 4 + j;              // 0..2047
        int k = idx >> 5, r = idx & 31;
        float v = g_e[(b * CR + k) * NPIX + n0 + r];
        s_A2[k * 32 + r] = make_float2(v, v);
    }

    // B panel: bf16, cp.async 128KB
    {
        unsigned sB = (unsigned)__cvta_generic_to_shared(s_B8);
        const char* src_base = (const char*)g_ebf + ((size_t)b * CR * NPIX + m0) * 2;
        #pragma unroll
        for (int j = 0; j < 16; j++) {
            int gidx = t + j * 512;        // 0..8191
            int k  = gidx >> 7;            // row
            int ch = gidx & 127;           // 16B chunk in row
            CP_ASYNC16(sB + (unsigned)(k * 2048 + ch * 16),
                       src_base + (size_t)k * NPIX * 2 + ch * 16);
        }
        CP_COMMIT();
        CP_WAIT0();
    }
    __syncthreads();

    const int rg = t >> 7;          // 0..3  -> rows rg*8..+7
    const int c0 = (t & 127) * 8;   // 8 cols

    unsigned long long acc[8][4];
    #pragma unroll
    for (int r = 0; r < 8; r++)
        #pragma unroll
        for (int cp = 0; cp < 4; cp++) acc[r][cp] = 0ull;

    #pragma unroll 4
    for (int k = 0; k < CR; k++) {
        const ulonglong2* Ap = (const ulonglong2*)(s_A2 + k * 32 + rg * 8);
        ulonglong2 a01 = Ap[0], a23 = Ap[1], a45 = Ap[2], a67 = Ap[3];

        uint4 braw = *(const uint4*)(s_B8 + k * 2048 + c0 * 2);
        unsigned long long b0, b1, b2, b3;
        PACK2(b0, __uint_as_float(braw.x << 16), __uint_as_float(braw.x & 0xffff0000u));
        PACK2(b1, __uint_as_float(braw.y << 16), __uint_as_float(braw.y & 0xffff0000u));
        PACK2(b2, __uint_as_float(braw.z << 16), __uint_as_float(braw.z & 0xffff0000u));
        PACK2(b3, __uint_as_float(braw.w << 16), __uint_as_float(braw.w & 0xffff0000u));

        FFMA2(acc[0][0], a01.x, b0); FFMA2(acc[0][1], a01.x, b1);
        FFMA2(acc[0][2], a01.x, b2); FFMA2(acc[0][3], a01.x, b3);
        FFMA2(acc[1][0], a01.y, b0); FFMA2(acc[1][1], a01.y, b1);
        FFMA2(acc[1][2], a01.y, b2); FFMA2(acc[1][3], a01.y, b3);
        FFMA2(acc[2][0], a23.x, b0); FFMA2(acc[2][1], a23.x, b1);
        FFMA2(acc[2][2], a23.x, b2); FFMA2(acc[2][3], a23.x, b3);
        FFMA2(acc[3][0], a23.y, b0); FFMA2(acc[3][1], a23.y, b1);
        FFMA2(acc[3][2], a23.y, b2); FFMA2(acc[3][3], a23.y, b3);
        FFMA2(acc[4][0], a45.x, b0); FFMA2(acc[4][1], a45.x, b1);
        FFMA2(acc[4][2], a45.x, b2); FFMA2(acc[4][3], a45.x, b3);
        FFMA2(acc[5][0], a45.y, b0); FFMA2(acc[5][1], a45.y, b1);
        FFMA2(acc[5][2], a45.y, b2); FFMA2(acc[5][3], a45.y, b3);
        FFMA2(acc[6][0], a67.x, b0); FFMA2(acc[6][1], a67.x, b1);
        FFMA2(acc[6][2], a67.x, b2); FFMA2(acc[6][3], a67.x, b3);
        FFMA2(acc[7][0], a67.y, b0); FFMA2(acc[7][1], a67.y, b1);
        FFMA2(acc[7][2], a67.y, b2); FFMA2(acc[7][3], a67.y, b3);
    }

    // filter epilogue: append candidates (rare) to per-row lists
    const int nbase = n0 + rg * 8;
    #pragma unroll
    for (int r = 0; r < 8; r++) {
        const int n = nbase + r;
        const float thr = g_norm[b * NPIX + n] - 1.4f;
        int* cl = g_cidx + ((size_t)(b * NPIX + n) << 12);
        #pragma unroll
        for (int cp = 0; cp < 4; cp++) {
            F2U u; u.u = acc[r][cp];
            const int m = m0 + c0 + cp * 2;
            if (u.f.x > thr) { int p = atomicAdd(&g_cnt[b * NPIX + n], 1); cl[p] = m; }
            if (u.f.y > thr) { int p = atomicAdd(&g_cnt[b * NPIX + n], 1); cl[p] = m + 1; }
        }
    }
}

// ---------------------------------------------------------------------------
// Solve kernel: exact fp32 dots over candidate list, exact max, Michelot from
// tau0 = Mex - 1, scatter out[:,m] += p * x[:,n].
// ---------------------------------------------------------------------------
__global__ __launch_bounds__(256) void solve_scatter_kernel(float* __restrict__ out)
{
    __shared__ int   s_idx[CAP];     // 16KB
    __shared__ float s_val[CAP];     // 16KB
    __shared__ float s_rf[8];
    __shared__ int   s_ri[8];
    __shared__ float s_Mex;
    __shared__ int   s_pk;
    __shared__ int   s_pidx[1024];
    __shared__ float s_pv[1024];

    const int n    = blockIdx.x;
    const int b    = blockIdx.y;
    const int t    = threadIdx.x;
    const int wid  = t >> 5;
    const int lane = t & 31;

    const int c = g_cnt[b * NPIX + n];
    if (t == 0) s_pk = 0;
    {
        const int* cl = g_cidx + ((size_t)(b * NPIX + n) << 12);
        for (int j = t; j < c; j += 256) s_idx[j] = cl[j];
    }
    __syncthreads();

    // exact fp32 dots (warp per candidate, 8 warps)
    {
        const float2 en = *(const float2*)&g_et[(size_t)(b * NPIX + n) * CR + lane * 2];
        for (int j = wid; j < c; j += 8) {
            int mcol = s_idx[j];
            float2 em = *(const float2*)&g_et[(size_t)(b * NPIX + mcol) * CR + lane * 2];
            float sum = en.x * em.x + en.y * em.y;
            #pragma unroll
            for (int o = 16; o; o >>= 1) sum += __shfl_xor_sync(0xffffffffu, sum, o);
            if (lane == 0) s_val[j] = sum;
        }
    }
    __syncthreads();

    // exact max over candidates (true row max is provably among them)
    {
        float mm = -3.0e38f;
        for (int j = t; j < c; j += 256) mm = fmaxf(mm, s_val[j]);
        #pragma unroll
        for (int o = 16; o; o >>= 1) mm = fmaxf(mm, __shfl_xor_sync(0xffffffffu, mm, o));
        if (lane == 0) s_rf[wid] = mm;
        __syncthreads();
        if (t == 0) {
            float v = s_rf[0];
            #pragma unroll
            for (int w = 1; w < 8; w++) v = fmaxf(v, s_rf[w]);
            s_Mex = v;
        }
        __syncthreads();
    }
    const float Mex = s_Mex;

    // Michelot on z' = val - Mex, starting tau0 = -1 (valid lower bound of tau)
    float tau = -1.0f;
    int prev = -1;
    for (int it = 0; it < 32; it++) {
        float ss = 0.f; int cnt = 0;
        for (int j = t; j < c; j += 256) {
            float z = s_val[j] - Mex;
            if (z > tau) { ss += z; cnt++; }
        }
        #pragma unroll
        for (int o = 16; o; o >>= 1) {
            ss  += __shfl_xor_sync(0xffffffffu, ss, o);
            cnt += __shfl_xor_sync(0xffffffffu, cnt, o);
        }
        if (lane == 0) { s_rf[wid] = ss; s_ri[wid] = cnt; }
        __syncthreads();
        float tss = 0.f; int tcn = 0;
        #pragma unroll
        for (int w = 0; w < 8; w++) { tss += s_rf[w]; tcn += s_ri[w]; }
        __syncthreads();
        tau = (tss - 1.f) / (float)tcn;
        if (tcn == prev) break;
        prev = tcn;
    }

    // positive-support compaction (ballot-aggregated)
    const unsigned lt_mask = (1u << lane) - 1u;
    for (int j0 = 0; j0 < c; j0 += 256) {
        int j = j0 + t;
        float p = 0.f;
        bool pos = false;
        if (j < c) {
            p = s_val[j] - Mex - tau;
            pos = p > 0.f;
        }
        unsigned mk = __ballot_sync(0xffffffffu, pos);
        int base = 0;
        if (lane == 0 && mk) base = atomicAdd(&s_pk, __popc(mk));
        base = __shfl_sync(0xffffffffu, base, 0);
        if (pos) {
            int pi = base + __popc(mk & lt_mask);
            if (pi < 1024) { s_pidx[pi] = s_idx[j]; s_pv[pi] = p; }
        }
    }
    __syncthreads();

    const float xv = g_xt[(size_t)(b * NPIX + n) * CIN + t];
    float* ob = out + (size_t)b * CIN * NPIX;
    if (s_pk <= 1024) {
        const int kp = s_pk;
        for (int jj = 0; jj < kp; jj++)
            atomicAdd(&ob[(size_t)t * NPIX + s_pidx[jj]], s_pv[jj] * xv);
    } else {
        // fallback (support > 1024): direct scan, compacted list unused
        for (int j = 0; j < c; j++) {
            float p = s_val[j] - Mex - tau;
            if (p > 0.f)
                atomicAdd(&ob[(size_t)t * NPIX + s_idx[j]], p * xv);
        }
    }
}

// ---------------------------------------------------------------------------
extern "C" void kernel_launch(void* const* d_in, const int* in_sizes, int n_in,
                              void* d_out, int out_size)
{
    const float* x      = (const float*)d_in[0];
    const float* conv_w = (const float*)d_in[1];
    const float* conv_b = (const float*)d_in[2];
    const float* gamma  = (const float*)d_in[3];
    const float* beta   = (const float*)d_in[4];
    const float* mean   = (const float*)d_in[5];
    const float* var    = (const float*)d_in[6];
    const float* prelu  = (const float*)d_in[7];
    float* out = (float*)d_out;

    cudaFuncSetAttribute(gemm_filter_kernel,
                         cudaFuncAttributeMaxDynamicSharedMemorySize, GEMM_SMEM);

    init_transpose_kernel<<<dim3(NPIX / 32, CIN / 32, BATCH), dim3(32, 8)>>>(x, out);

    int wtot = CR * CIN * 9;
    wt_transpose_kernel<<<(wtot + 255) / 256, 256>>>(conv_w);

    conv_partial_kernel<<<dim3(HH, 4, BATCH), 256>>>(x);

    int etot4 = BATCH * CR * NPIX / 4;
    conv_epilogue_kernel<<<(etot4 + 255) / 256, 256>>>(
        conv_b, gamma, beta, mean, var, prelu);

    gemm_filter_kernel<<<dim3(NPIX / 1024, NPIX / 32, BATCH), 512, GEMM_SMEM>>>();

    solve_scatter_kernel<<<dim3(NPIX, BATCH), 256>>>(out);
}

// round 8
// speedup vs baseline: 1.3951x; 1.3751x over previous
#include <cuda_runtime.h>
#include <cuda_bf16.h>

#define BATCH 2
#define CIN   256
#define CR    64
#define HH    64
#define WW    64
#define NPIX  4096
#define CAP   4096

#define FFMA2(d, a, b) asm("fma.rn.f32x2 %0, %1, %2, %0;" : "+l"(d) : "l"(a), "l"(b))
#define PACK2(d, lo, hi) asm("mov.b64 %0, {%1, %2};" : "=l"(d) : "f"(lo), "f"(hi))
#define CP_ASYNC16(dst, src) asm volatile("cp.async.cg.shared.global [%0], [%1], 16;" :: "r"(dst), "l"(src))
#define CP_COMMIT()  asm volatile("cp.async.commit_group;")
#define CP_WAIT0()   asm volatile("cp.async.wait_group 0;")
#define SWZ(o) ((o) ^ (((o) >> 3) & 0x70))

union F2U { unsigned long long u; float2 f; };

// device scratch
__device__ float  g_et [BATCH * NPIX * CR];          // e fp32 [n][k] (exact rescue)
__device__ __nv_bfloat16 g_etbf[BATCH * NPIX * CR];  // e bf16 [n][k] (mma operands)
__device__ float2 g_wt2[CIN * 9 * CR];               // dup-packed weights
__device__ float  g_part[4 * BATCH * CR * NPIX];     // conv partials
__device__ float  g_xt [BATCH * NPIX * CIN];         // x transposed [b][n][c]
__device__ float  g_norm[BATCH * NPIX];              // ||e_n||^2 exact
__device__ int    g_cnt [BATCH * NPIX];              // candidate counts
__device__ int    g_cidx[(size_t)BATCH * NPIX * CAP];// candidate column lists

// ---------------------------------------------------------------------------
// out = x  AND  g_xt[b][n][c] = x[b][c][n]
// ---------------------------------------------------------------------------
__global__ __launch_bounds__(256) void init_transpose_kernel(
    const float* __restrict__ x, float* __restrict__ out)
{
    __shared__ float s[32][33];
    const int b  = blockIdx.z;
    const int n0 = blockIdx.x * 32;
    const int c0 = blockIdx.y * 32;
    const int tx = threadIdx.x, ty = threadIdx.y;
    #pragma unroll
    for (int j = 0; j < 4; j++) {
        int c = c0 + ty + j * 8;
        float v = x[(b * CIN + c) * NPIX + n0 + tx];
        out[(b * CIN + c) * NPIX + n0 + tx] = v;
        s[ty + j * 8][tx] = v;
    }
    __syncthreads();
    #pragma unroll
    for (int j = 0; j < 4; j++) {
        int n = n0 + ty + j * 8;
        g_xt[(b * NPIX + n) * CIN + c0 + tx] = s[tx][ty + j * 8];
    }
}

// ---------------------------------------------------------------------------
// weight transpose + zero norm/cnt
// ---------------------------------------------------------------------------
__global__ void wt_transpose_kernel(const float* __restrict__ w) {
    int i = blockIdx.x * blockDim.x + threadIdx.x;
    if (i < BATCH * NPIX) { g_cnt[i] = 0; g_norm[i] = 0.f; }
    if (i < CR * CIN * 9) {
        int co = i / (CIN * 9);
        int q  = i % (CIN * 9);
        float v = w[i];
        g_wt2[q * CR + co] = make_float2(v, v);
    }
}

// ---------------------------------------------------------------------------
// conv3x3 partial (ci-split x4), f32x2
// ---------------------------------------------------------------------------
__global__ __launch_bounds__(256) void conv_partial_kernel(const float* __restrict__ x)
{
    __shared__ __align__(16) float  s_x[8][3][68];
    __shared__ __align__(16) float2 s_w[8][9][64];

    const int h   = blockIdx.x;
    const int cis = blockIdx.y;
    const int b   = blockIdx.z;
    const int cib = cis * 64;
    const int t   = threadIdx.x;
    const int cg  = t >> 4;
    const int px0 = (t & 15) * 4;

    unsigned long long acc[4][2];
    #pragma unroll
    for (int j = 0; j < 4; j++) { acc[j][0] = 0ull; acc[j][1] = 0ull; }

    for (int ci0 = cib; ci0 < cib + 64; ci0 += 8) {
        __syncthreads();
        for (int idx = t; idx < 8 * 3 * 66; idx += 256) {
            int ci = idx / 198;
            int rem = idx % 198;
            int r  = rem / 66;
            int c2 = rem % 66;
            int hh = h - 1 + r;
            int cc = c2 - 1;
            float v = 0.f;
            if (hh >= 0 && hh < HH && cc >= 0 && cc < WW)
                v = x[((b * CIN + ci0 + ci) * HH + hh) * WW + cc];
            s_x[ci][r][c2] = v;
        }
        for (int idx = t; idx < 8 * 9 * 64; idx += 256) {
            int ci = idx / 576;
            int rem = idx % 576;
            int kk = rem >> 6;
            int co = rem & 63;
            s_w[ci][kk][co] = g_wt2[((ci0 + ci) * 9 + kk) * CR + co];
        }
        __syncthreads();

        #pragma unroll
        for (int ci = 0; ci < 8; ci++) {
            #pragma unroll
            for (int kh = 0; kh < 3; kh++) {
                float4 xa  = *(const float4*)&s_x[ci][kh][px0];
                float2 xb2 = *(const float2*)&s_x[ci][kh][px0 + 4];
                float xv[6] = {xa.x, xa.y, xa.z, xa.w, xb2.x, xb2.y};
                #pragma unroll
                for (int kw = 0; kw < 3; kw++) {
                    unsigned long long xp0, xp1;
                    PACK2(xp0, xv[kw],     xv[kw + 1]);
                    PACK2(xp1, xv[kw + 2], xv[kw + 3]);
                    ulonglong2 w01 = *(const ulonglong2*)&s_w[ci][kh * 3 + kw][cg * 4];
                    ulonglong2 w23 = *(const ulonglong2*)&s_w[ci][kh * 3 + kw][cg * 4 + 2];
                    FFMA2(acc[0][0], w01.x, xp0);  FFMA2(acc[0][1], w01.x, xp1);
                    FFMA2(acc[1][0], w01.y, xp0);  FFMA2(acc[1][1], w01.y, xp1);
                    FFMA2(acc[2][0], w23.x, xp0);  FFMA2(acc[2][1], w23.x, xp1);
                    FFMA2(acc[3][0], w23.y, xp0);  FFMA2(acc[3][1], w23.y, xp1);
                }
            }
        }
    }

    float* dst = g_part + ((cis * BATCH + b) * CR) * NPIX;
    #pragma unroll
    for (int j = 0; j < 4; j++) {
        F2U u0, u1; u0.u = acc[j][0]; u1.u = acc[j][1];
        float4 v = make_float4(u0.f.x, u0.f.y, u1.f.x, u1.f.y);
        int co = cg * 4 + j;
        *(float4*)&dst[co * NPIX + h * WW + px0] = v;
    }
}

// ---------------------------------------------------------------------------
// epilogue: sum partials + bias + BN + PReLU -> g_et, g_etbf, g_norm
// ---------------------------------------------------------------------------
__global__ __launch_bounds__(256) void conv_epilogue_kernel(
    const float* __restrict__ cb, const float* __restrict__ gamma,
    const float* __restrict__ beta, const float* __restrict__ mean,
    const float* __restrict__ var, const float* __restrict__ prelu)
{
    const int i = blockIdx.x * blockDim.x + threadIdx.x;
    const int per_b4 = CR * NPIX / 4;
    if (i >= BATCH * per_b4) return;
    const int b   = i / per_b4;
    const int rem = i % per_b4;
    const int co  = rem / (NPIX / 4);
    const int n4  = rem % (NPIX / 4);

    float4 v0 = ((const float4*)g_part)[(0 * BATCH + b) * per_b4 + rem];
    float4 v1 = ((const float4*)g_part)[(1 * BATCH + b) * per_b4 + rem];
    float4 v2 = ((const float4*)g_part)[(2 * BATCH + b) * per_b4 + rem];
    float4 v3 = ((const float4*)g_part)[(3 * BATCH + b) * per_b4 + rem];
    float4 s;
    s.x = (v0.x + v1.x) + (v2.x + v3.x);
    s.y = (v0.y + v1.y) + (v2.y + v3.y);
    s.z = (v0.z + v1.z) + (v2.z + v3.z);
    s.w = (v0.w + v1.w) + (v2.w + v3.w);

    const float sc    = gamma[co] * rsqrtf(var[co] + 1e-5f);
    const float base  = (cb[co] - mean[co]) * sc + beta[co];
    const float slope = prelu[0];
    float y;
    y = s.x * sc + base; s.x = (y >= 0.f) ? y : slope * y;
    y = s.y * sc + base; s.y = (y >= 0.f) ? y : slope * y;
    y = s.z * sc + base; s.z = (y >= 0.f) ? y : slope * y;
    y = s.w * sc + base; s.w = (y >= 0.f) ? y : slope * y;

    const int nb = n4 * 4;
    float* et = g_et + (b * NPIX + nb) * CR + co;
    __nv_bfloat16* etb = g_etbf + (b * NPIX + nb) * CR + co;
    et[0 * CR] = s.x;  etb[0 * CR] = __float2bfloat16(s.x);
    et[1 * CR] = s.y;  etb[1 * CR] = __float2bfloat16(s.y);
    et[2 * CR] = s.z;  etb[2 * CR] = __float2bfloat16(s.z);
    et[3 * CR] = s.w;  etb[3 * CR] = __float2bfloat16(s.w);

    atomicAdd(&g_norm[b * NPIX + nb + 0], s.x * s.x);
    atomicAdd(&g_norm[b * NPIX + nb + 1], s.y * s.y);
    atomicAdd(&g_norm[b * NPIX + nb + 2], s.z * s.z);
    atomicAdd(&g_norm[b * NPIX + nb + 3], s.w * s.w);
}

// ---------------------------------------------------------------------------
// Tensor-core GEMM + filter: z = e_bf . e_bf^T via mma.sync bf16 (HMMA).
// CTA tile 64 rows x 256 cols, 8 warps = 4 row-groups x 2 col-groups.
// Candidates (z > norm_n - 2.0) appended to per-row lists; sim never stored.
// ---------------------------------------------------------------------------
#define MMA(d, a0, a1, a2, a3, b0, b1)                                        \
    asm volatile("mma.sync.aligned.m16n8k16.row.col.f32.bf16.bf16.f32 "       \
                 "{%0,%1,%2,%3}, {%4,%5,%6,%7}, {%8,%9}, {%0,%1,%2,%3};"      \
                 : "+f"(d[0]), "+f"(d[1]), "+f"(d[2]), "+f"(d[3])             \
                 : "r"(a0), "r"(a1), "r"(a2), "r"(a3), "r"(b0), "r"(b1))

#define LDSM4(r0, r1, r2, r3, addr)                                           \
    asm volatile("ldmatrix.sync.aligned.m8n8.x4.shared.b16 {%0,%1,%2,%3}, [%4];" \
                 : "=r"(r0), "=r"(r1), "=r"(r2), "=r"(r3) : "r"(addr))

__global__ __launch_bounds__(256) void gemm_filter_mma_kernel()
{
    __shared__ __align__(1024) char s_A[64 * 128];    // 64 rows x 128B (SW128)
    __shared__ __align__(1024) char s_B[256 * 128];   // 256 rows x 128B

    const int b  = blockIdx.z;
    const int n0 = blockIdx.y * 64;
    const int m0 = blockIdx.x * 256;
    const int t  = threadIdx.x;
    const int wid  = t >> 5;
    const int lane = t & 31;
    const int rg = wid >> 1;    // 0..3 row-group (16 rows each)
    const int cg = wid & 1;     // 0..1 col-group (128 cols each)
    const int bN = b * NPIX;

    // cp.async tile loads (SW128-swizzled)
    {
        unsigned sa = (unsigned)__cvta_generic_to_shared(s_A);
        unsigned sb = (unsigned)__cvta_generic_to_shared(s_B);
        const char* Ab = (const char*)g_etbf + (size_t)(bN + n0) * 128;
        const char* Bb = (const char*)g_etbf + (size_t)(bN + m0) * 128;
        #pragma unroll
        for (int j = 0; j < 2; j++) {
            int idx = t + j * 256;                 // 0..511
            unsigned off = (unsigned)((idx >> 3) * 128 + (idx & 7) * 16);
            CP_ASYNC16(sa + SWZ(off), Ab + off);
        }
        #pragma unroll
        for (int j = 0; j < 8; j++) {
            int idx = t + j * 256;                 // 0..2047
            unsigned off = (unsigned)((idx >> 3) * 128 + (idx & 7) * 16);
            CP_ASYNC16(sb + SWZ(off), Bb + off);
        }
        CP_COMMIT();
        CP_WAIT0();
    }
    __syncthreads();

    float acc[16][4];
    #pragma unroll
    for (int nb = 0; nb < 16; nb++)
        #pragma unroll
        for (int q = 0; q < 4; q++) acc[nb][q] = 0.f;

    const unsigned saB = (unsigned)__cvta_generic_to_shared(s_A);
    const unsigned sbB = (unsigned)__cvta_generic_to_shared(s_B);
    const unsigned hb  = (unsigned)((lane >> 4) * 16);      // k-half byte offset
    const unsigned rA  = (unsigned)((rg * 16 + (lane & 15)) * 128);
    const unsigned rBb = (unsigned)((cg * 128 + (lane & 15)) * 128);

    #pragma unroll
    for (int kc = 0; kc < 4; kc++) {
        unsigned a0, a1, a2, a3;
        LDSM4(a0, a1, a2, a3, saB + SWZ(rA + kc * 32 + hb));
        #pragma unroll
        for (int ng = 0; ng < 8; ng++) {
            unsigned b0, b1, b2, b3;
            LDSM4(b0, b1, b2, b3, sbB + SWZ(rBb + (unsigned)(ng * 16 * 128) + kc * 32 + hb));
            MMA(acc[2 * ng],     a0, a1, a2, a3, b0, b2);
            MMA(acc[2 * ng + 1], a0, a1, a2, a3, b1, b3);
        }
    }

    // filter epilogue on register fragments:
    // d0:(r0,c) d1:(r0,c+1) d2:(r1,c) d3:(r1,c+1); r0 = rg*16 + lane/4, r1 = r0+8
    const int nrow0 = bN + n0 + rg * 16 + (lane >> 2);
    const int nrow1 = nrow0 + 8;
    const float thr0 = g_norm[nrow0] - 2.0f;
    const float thr1 = g_norm[nrow1] - 2.0f;
    int* cl0 = g_cidx + ((size_t)nrow0 << 12);
    int* cl1 = g_cidx + ((size_t)nrow1 << 12);
    const int cbase = m0 + cg * 128 + 2 * (lane & 3);

    #pragma unroll
    for (int nb = 0; nb < 16; nb++) {
        const int col = cbase + nb * 8;
        if (acc[nb][0] > thr0) { int p = atomicAdd(&g_cnt[nrow0], 1); cl0[p] = col; }
        if (acc[nb][1] > thr0) { int p = atomicAdd(&g_cnt[nrow0], 1); cl0[p] = col + 1; }
        if (acc[nb][2] > thr1) { int p = atomicAdd(&g_cnt[nrow1], 1); cl1[p] = col; }
        if (acc[nb][3] > thr1) { int p = atomicAdd(&g_cnt[nrow1], 1); cl1[p] = col + 1; }
    }
}

// ---------------------------------------------------------------------------
// Solve kernel: exact fp32 dots over candidates, Michelot from tau0=-1, scatter
// ---------------------------------------------------------------------------
__global__ __launch_bounds__(256) void solve_scatter_kernel(float* __restrict__ out)
{
    __shared__ int   s_idx[CAP];
    __shared__ float s_val[CAP];
    __shared__ float s_rf[8];
    __shared__ int   s_ri[8];
    __shared__ float s_Mex;
    __shared__ int   s_pk;
    __shared__ int   s_pidx[1024];
    __shared__ float s_pv[1024];

    const int n    = blockIdx.x;
    const int b    = blockIdx.y;
    const int t    = threadIdx.x;
    const int wid  = t >> 5;
    const int lane = t & 31;

    const int c = g_cnt[b * NPIX + n];
    if (t == 0) s_pk = 0;
    {
        const int* cl = g_cidx + ((size_t)(b * NPIX + n) << 12);
        for (int j = t; j < c; j += 256) s_idx[j] = cl[j];
    }
    __syncthreads();

    // exact fp32 dots (warp per candidate)
    {
        const float2 en = *(const float2*)&g_et[(size_t)(b * NPIX + n) * CR + lane * 2];
        for (int j = wid; j < c; j += 8) {
            int mcol = s_idx[j];
            float2 em = *(const float2*)&g_et[(size_t)(b * NPIX + mcol) * CR + lane * 2];
            float sum = en.x * em.x + en.y * em.y;
            #pragma unroll
            for (int o = 16; o; o >>= 1) sum += __shfl_xor_sync(0xffffffffu, sum, o);
            if (lane == 0) s_val[j] = sum;
        }
    }
    __syncthreads();

    // exact max over candidates
    {
        float mm = -3.0e38f;
        for (int j = t; j < c; j += 256) mm = fmaxf(mm, s_val[j]);
        #pragma unroll
        for (int o = 16; o; o >>= 1) mm = fmaxf(mm, __shfl_xor_sync(0xffffffffu, mm, o));
        if (lane == 0) s_rf[wid] = mm;
        __syncthreads();
        if (t == 0) {
            float v = s_rf[0];
            #pragma unroll
            for (int w = 1; w < 8; w++) v = fmaxf(v, s_rf[w]);
            s_Mex = v;
        }
        __syncthreads();
    }
    const float Mex = s_Mex;

    // Michelot from tau0 = -1 (valid lower bound)
    float tau = -1.0f;
    int prev = -1;
    for (int it = 0; it < 32; it++) {
        float ss = 0.f; int cnt = 0;
        for (int j = t; j < c; j += 256) {
            float z = s_val[j] - Mex;
            if (z > tau) { ss += z; cnt++; }
        }
        #pragma unroll
        for (int o = 16; o; o >>= 1) {
            ss  += __shfl_xor_sync(0xffffffffu, ss, o);
            cnt += __shfl_xor_sync(0xffffffffu, cnt, o);
        }
        if (lane == 0) { s_rf[wid] = ss; s_ri[wid] = cnt; }
        __syncthreads();
        float tss = 0.f; int tcn = 0;
        #pragma unroll
        for (int w = 0; w < 8; w++) { tss += s_rf[w]; tcn += s_ri[w]; }
        __syncthreads();
        tau = (tss - 1.f) / (float)tcn;
        if (tcn == prev) break;
        prev = tcn;
    }

    // positive-support compaction (ballot-aggregated)
    const unsigned lt_mask = (1u << lane) - 1u;
    for (int j0 = 0; j0 < c; j0 += 256) {
        int j = j0 + t;
        float p = 0.f;
        bool pos = false;
        if (j < c) {
            p = s_val[j] - Mex - tau;
            pos = p > 0.f;
        }
        unsigned mk = __ballot_sync(0xffffffffu, pos);
        int base = 0;
        if (lane == 0 && mk) base = atomicAdd(&s_pk, __popc(mk));
        base = __shfl_sync(0xffffffffu, base, 0);
        if (pos) {
            int pi = base + __popc(mk & lt_mask);
            if (pi < 1024) { s_pidx[pi] = s_idx[j]; s_pv[pi] = p; }
        }
    }
    __syncthreads();

    const float xv = g_xt[(size_t)(b * NPIX + n) * CIN + t];
    float* ob = out + (size_t)b * CIN * NPIX;
    if (s_pk <= 1024) {
        const int kp = s_pk;
        for (int jj = 0; jj < kp; jj++)
            atomicAdd(&ob[(size_t)t * NPIX + s_pidx[jj]], s_pv[jj] * xv);
    } else {
        for (int j = 0; j < c; j++) {
            float p = s_val[j] - Mex - tau;
            if (p > 0.f)
                atomicAdd(&ob[(size_t)t * NPIX + s_idx[j]], p * xv);
        }
    }
}

// ---------------------------------------------------------------------------
extern "C" void kernel_launch(void* const* d_in, const int* in_sizes, int n_in,
                              void* d_out, int out_size)
{
    const float* x      = (const float*)d_in[0];
    const float* conv_w = (const float*)d_in[1];
    const float* conv_b = (const float*)d_in[2];
    const float* gamma  = (const float*)d_in[3];
    const float* beta   = (const float*)d_in[4];
    const float* mean   = (const float*)d_in[5];
    const float* var    = (const float*)d_in[6];
    const float* prelu  = (const float*)d_in[7];
    float* out = (float*)d_out;

    init_transpose_kernel<<<dim3(NPIX / 32, CIN / 32, BATCH), dim3(32, 8)>>>(x, out);

    int wtot = CR * CIN * 9;
    wt_transpose_kernel<<<(wtot + 255) / 256, 256>>>(conv_w);

    conv_partial_kernel<<<dim3(HH, 4, BATCH), 256>>>(x);

    int etot4 = BATCH * CR * NPIX / 4;
    conv_epilogue_kernel<<<(etot4 + 255) / 256, 256>>>(
        conv_b, gamma, beta, mean, var, prelu);

    gemm_filter_mma_kernel<<<dim3(NPIX / 256, NPIX / 64, BATCH), 256>>>();

    solve_scatter_kernel<<<dim3(NPIX, BATCH), 256>>>(out);
}

// round 9
// speedup vs baseline: 1.4627x; 1.0484x over previous
#include <cuda_runtime.h>
#include <cuda_bf16.h>

#define BATCH 2
#define CIN   256
#define CR    64
#define HH    64
#define WW    64
#define NPIX  4096
#define CAP   4096

#define FFMA2(d, a, b) asm("fma.rn.f32x2 %0, %1, %2, %0;" : "+l"(d) : "l"(a), "l"(b))
#define PACK2(d, lo, hi) asm("mov.b64 %0, {%1, %2};" : "=l"(d) : "f"(lo), "f"(hi))
#define CP_ASYNC16(dst, src) asm volatile("cp.async.cg.shared.global [%0], [%1], 16;" :: "r"(dst), "l"(src))
#define CP_COMMIT()  asm volatile("cp.async.commit_group;")
#define CP_WAIT0()   asm volatile("cp.async.wait_group 0;")
#define SWZ(o) ((o) ^ (((o) >> 3) & 0x70))

union F2U { unsigned long long u; float2 f; };

// device scratch
__device__ float  g_et [BATCH * NPIX * CR];          // e fp32 [n][k] (exact rescue)
__device__ __nv_bfloat16 g_etbf[BATCH * NPIX * CR];  // e bf16 [n][k] (mma operands)
__device__ float2 g_wt2[CIN * 9 * CR];               // dup-packed weights
__device__ float  g_part[4 * BATCH * CR * NPIX];     // conv partials
__device__ float  g_xt [BATCH * NPIX * CIN];         // x transposed [b][n][c]
__device__ float  g_norm[BATCH * NPIX];              // ||e_n||^2 exact
__device__ int    g_cnt [BATCH * NPIX];              // candidate counts
__device__ int    g_cidx[(size_t)BATCH * NPIX * CAP];// candidate column lists
__device__ float  g_outt[BATCH * NPIX * CIN];        // transposed accumulation [b][m][c]

// ---------------------------------------------------------------------------
// wt transpose + zero outt/cnt  (grid 2048 x 256)
// ---------------------------------------------------------------------------
__global__ __launch_bounds__(256) void wt_zero_kernel(const float* __restrict__ w) {
    int i = blockIdx.x * blockDim.x + threadIdx.x;    // 0..524287
    ((float4*)g_outt)[i] = make_float4(0.f, 0.f, 0.f, 0.f);
    if (i < CR * CIN * 9) {
        int co = i / (CIN * 9);
        int q  = i % (CIN * 9);
        float v = w[i];
        g_wt2[q * CR + co] = make_float2(v, v);
    }
    if (i < BATCH * NPIX) g_cnt[i] = 0;
}

// ---------------------------------------------------------------------------
// g_xt[b][n][c] = x[b][c][n]
// ---------------------------------------------------------------------------
__global__ __launch_bounds__(256) void init_transpose_kernel(const float* __restrict__ x)
{
    __shared__ float s[32][33];
    const int b  = blockIdx.z;
    const int n0 = blockIdx.x * 32;
    const int c0 = blockIdx.y * 32;
    const int tx = threadIdx.x, ty = threadIdx.y;
    #pragma unroll
    for (int j = 0; j < 4; j++) {
        int c = c0 + ty + j * 8;
        s[ty + j * 8][tx] = x[(b * CIN + c) * NPIX + n0 + tx];
    }
    __syncthreads();
    #pragma unroll
    for (int j = 0; j < 4; j++) {
        int n = n0 + ty + j * 8;
        g_xt[(b * NPIX + n) * CIN + c0 + tx] = s[tx][ty + j * 8];
    }
}

// ---------------------------------------------------------------------------
// conv3x3 partial (ci-split x4), f32x2
// ---------------------------------------------------------------------------
__global__ __launch_bounds__(256) void conv_partial_kernel(const float* __restrict__ x)
{
    __shared__ __align__(16) float  s_x[8][3][68];
    __shared__ __align__(16) float2 s_w[8][9][64];

    const int h   = blockIdx.x;
    const int cis = blockIdx.y;
    const int b   = blockIdx.z;
    const int cib = cis * 64;
    const int t   = threadIdx.x;
    const int cg  = t >> 4;
    const int px0 = (t & 15) * 4;

    unsigned long long acc[4][2];
    #pragma unroll
    for (int j = 0; j < 4; j++) { acc[j][0] = 0ull; acc[j][1] = 0ull; }

    for (int ci0 = cib; ci0 < cib + 64; ci0 += 8) {
        __syncthreads();
        for (int idx = t; idx < 8 * 3 * 66; idx += 256) {
            int ci = idx / 198;
            int rem = idx % 198;
            int r  = rem / 66;
            int c2 = rem % 66;
            int hh = h - 1 + r;
            int cc = c2 - 1;
            float v = 0.f;
            if (hh >= 0 && hh < HH && cc >= 0 && cc < WW)
                v = x[((b * CIN + ci0 + ci) * HH + hh) * WW + cc];
            s_x[ci][r][c2] = v;
        }
        for (int idx = t; idx < 8 * 9 * 64; idx += 256) {
            int ci = idx / 576;
            int rem = idx % 576;
            int kk = rem >> 6;
            int co = rem & 63;
            s_w[ci][kk][co] = g_wt2[((ci0 + ci) * 9 + kk) * CR + co];
        }
        __syncthreads();

        #pragma unroll
        for (int ci = 0; ci < 8; ci++) {
            #pragma unroll
            for (int kh = 0; kh < 3; kh++) {
                float4 xa  = *(const float4*)&s_x[ci][kh][px0];
                float2 xb2 = *(const float2*)&s_x[ci][kh][px0 + 4];
                float xv[6] = {xa.x, xa.y, xa.z, xa.w, xb2.x, xb2.y};
                #pragma unroll
                for (int kw = 0; kw < 3; kw++) {
                    unsigned long long xp0, xp1;
                    PACK2(xp0, xv[kw],     xv[kw + 1]);
                    PACK2(xp1, xv[kw + 2], xv[kw + 3]);
                    ulonglong2 w01 = *(const ulonglong2*)&s_w[ci][kh * 3 + kw][cg * 4];
                    ulonglong2 w23 = *(const ulonglong2*)&s_w[ci][kh * 3 + kw][cg * 4 + 2];
                    FFMA2(acc[0][0], w01.x, xp0);  FFMA2(acc[0][1], w01.x, xp1);
                    FFMA2(acc[1][0], w01.y, xp0);  FFMA2(acc[1][1], w01.y, xp1);
                    FFMA2(acc[2][0], w23.x, xp0);  FFMA2(acc[2][1], w23.x, xp1);
                    FFMA2(acc[3][0], w23.y, xp0);  FFMA2(acc[3][1], w23.y, xp1);
                }
            }
        }
    }

    float* dst = g_part + ((cis * BATCH + b) * CR) * NPIX;
    #pragma unroll
    for (int j = 0; j < 4; j++) {
        F2U u0, u1; u0.u = acc[j][0]; u1.u = acc[j][1];
        float4 v = make_float4(u0.f.x, u0.f.y, u1.f.x, u1.f.y);
        int co = cg * 4 + j;
        *(float4*)&dst[co * NPIX + h * WW + px0] = v;
    }
}

// ---------------------------------------------------------------------------
// epilogue: block = 32 n x 64 co. Coalesced slab reads, smem transpose,
// coalesced g_et/g_etbf row writes, norm via block reduction (no atomics).
// ---------------------------------------------------------------------------
__global__ __launch_bounds__(256) void conv_epilogue_kernel(
    const float* __restrict__ cb, const float* __restrict__ gamma,
    const float* __restrict__ beta, const float* __restrict__ mean,
    const float* __restrict__ var, const float* __restrict__ prelu)
{
    __shared__ float s_v[64][33];
    __shared__ float s_nrm[8][32];

    const int b    = blockIdx.y;
    const int n0   = blockIdx.x * 32;
    const int t    = threadIdx.x;
    const int w    = t >> 5;
    const int lane = t & 31;
    const float slope = prelu[0];

    float nacc = 0.f;
    #pragma unroll
    for (int j = 0; j < 8; j++) {
        const int co = w * 8 + j;
        const size_t off = (size_t)co * NPIX + n0 + lane;
        float v = g_part[((0 * BATCH + b) * CR) * NPIX + off]
                + g_part[((1 * BATCH + b) * CR) * NPIX + off]
                + g_part[((2 * BATCH + b) * CR) * NPIX + off]
                + g_part[((3 * BATCH + b) * CR) * NPIX + off];
        const float sc   = gamma[co] * rsqrtf(var[co] + 1e-5f);
        const float base = (cb[co] - mean[co]) * sc + beta[co];
        float y = v * sc + base;
        y = (y >= 0.f) ? y : slope * y;
        s_v[co][lane] = y;
        nacc += y * y;
    }
    s_nrm[w][lane] = nacc;
    __syncthreads();

    if (w == 0) {
        float s = 0.f;
        #pragma unroll
        for (int k = 0; k < 8; k++) s += s_nrm[k][lane];
        g_norm[b * NPIX + n0 + lane] = s;
    }

    // transposed writes: thread t -> n = t>>3, co8 = (t&7)*8
    const int n  = t >> 3;
    const int c8 = (t & 7) * 8;
    float vals[8];
    #pragma unroll
    for (int j = 0; j < 8; j++) vals[j] = s_v[c8 + j][n];

    float* et = g_et + ((size_t)(b * NPIX) + n0 + n) * CR + c8;
    *(float4*)et       = make_float4(vals[0], vals[1], vals[2], vals[3]);
    *(float4*)(et + 4) = make_float4(vals[4], vals[5], vals[6], vals[7]);

    unsigned q0, q1, q2, q3;
    asm("cvt.rn.bf16x2.f32 %0, %1, %2;" : "=r"(q0) : "f"(vals[1]), "f"(vals[0]));
    asm("cvt.rn.bf16x2.f32 %0, %1, %2;" : "=r"(q1) : "f"(vals[3]), "f"(vals[2]));
    asm("cvt.rn.bf16x2.f32 %0, %1, %2;" : "=r"(q2) : "f"(vals[5]), "f"(vals[4]));
    asm("cvt.rn.bf16x2.f32 %0, %1, %2;" : "=r"(q3) : "f"(vals[7]), "f"(vals[6]));
    *(uint4*)(g_etbf + ((size_t)(b * NPIX) + n0 + n) * CR + c8) = make_uint4(q0, q1, q2, q3);
}

// ---------------------------------------------------------------------------
// Tensor-core GEMM + filter (mma.sync bf16). CTA 64x256, cand if z > norm-2
// ---------------------------------------------------------------------------
#define MMA(d, a0, a1, a2, a3, b0, b1)                                        \
    asm volatile("mma.sync.aligned.m16n8k16.row.col.f32.bf16.bf16.f32 "       \
                 "{%0,%1,%2,%3}, {%4,%5,%6,%7}, {%8,%9}, {%0,%1,%2,%3};"      \
                 : "+f"(d[0]), "+f"(d[1]), "+f"(d[2]), "+f"(d[3])             \
                 : "r"(a0), "r"(a1), "r"(a2), "r"(a3), "r"(b0), "r"(b1))

#define LDSM4(r0, r1, r2, r3, addr)                                           \
    asm volatile("ldmatrix.sync.aligned.m8n8.x4.shared.b16 {%0,%1,%2,%3}, [%4];" \
                 : "=r"(r0), "=r"(r1), "=r"(r2), "=r"(r3) : "r"(addr))

__global__ __launch_bounds__(256) void gemm_filter_mma_kernel()
{
    __shared__ __align__(1024) char s_A[64 * 128];
    __shared__ __align__(1024) char s_B[256 * 128];

    const int b  = blockIdx.z;
    const int n0 = blockIdx.y * 64;
    const int m0 = blockIdx.x * 256;
    const int t  = threadIdx.x;
    const int wid  = t >> 5;
    const int lane = t & 31;
    const int rg = wid >> 1;
    const int cg = wid & 1;
    const int bN = b * NPIX;

    {
        unsigned sa = (unsigned)__cvta_generic_to_shared(s_A);
        unsigned sb = (unsigned)__cvta_generic_to_shared(s_B);
        const char* Ab = (const char*)g_etbf + (size_t)(bN + n0) * 128;
        const char* Bb = (const char*)g_etbf + (size_t)(bN + m0) * 128;
        #pragma unroll
        for (int j = 0; j < 2; j++) {
            int idx = t + j * 256;
            unsigned off = (unsigned)((idx >> 3) * 128 + (idx & 7) * 16);
            CP_ASYNC16(sa + SWZ(off), Ab + off);
        }
        #pragma unroll
        for (int j = 0; j < 8; j++) {
            int idx = t + j * 256;
            unsigned off = (unsigned)((idx >> 3) * 128 + (idx & 7) * 16);
            CP_ASYNC16(sb + SWZ(off), Bb + off);
        }
        CP_COMMIT();
        CP_WAIT0();
    }
    __syncthreads();

    float acc[16][4];
    #pragma unroll
    for (int nb = 0; nb < 16; nb++)
        #pragma unroll
        for (int q = 0; q < 4; q++) acc[nb][q] = 0.f;

    const unsigned saB = (unsigned)__cvta_generic_to_shared(s_A);
    const unsigned sbB = (unsigned)__cvta_generic_to_shared(s_B);
    const unsigned hb  = (unsigned)((lane >> 4) * 16);
    const unsigned rA  = (unsigned)((rg * 16 + (lane & 15)) * 128);
    const unsigned rBb = (unsigned)((cg * 128 + (lane & 15)) * 128);

    #pragma unroll
    for (int kc = 0; kc < 4; kc++) {
        unsigned a0, a1, a2, a3;
        LDSM4(a0, a1, a2, a3, saB + SWZ(rA + kc * 32 + hb));
        #pragma unroll
        for (int ng = 0; ng < 8; ng++) {
            unsigned b0, b1, b2, b3;
            LDSM4(b0, b1, b2, b3, sbB + SWZ(rBb + (unsigned)(ng * 16 * 128) + kc * 32 + hb));
            MMA(acc[2 * ng],     a0, a1, a2, a3, b0, b2);
            MMA(acc[2 * ng + 1], a0, a1, a2, a3, b1, b3);
        }
    }

    const int nrow0 = bN + n0 + rg * 16 + (lane >> 2);
    const int nrow1 = nrow0 + 8;
    const float thr0 = g_norm[nrow0] - 2.0f;
    const float thr1 = g_norm[nrow1] - 2.0f;
    int* cl0 = g_cidx + ((size_t)nrow0 << 12);
    int* cl1 = g_cidx + ((size_t)nrow1 << 12);
    const int cbase = m0 + cg * 128 + 2 * (lane & 3);

    #pragma unroll
    for (int nb = 0; nb < 16; nb++) {
        const int col = cbase + nb * 8;
        if (acc[nb][0] > thr0) { int p = atomicAdd(&g_cnt[nrow0], 1); cl0[p] = col; }
        if (acc[nb][1] > thr0) { int p = atomicAdd(&g_cnt[nrow0], 1); cl0[p] = col + 1; }
        if (acc[nb][2] > thr1) { int p = atomicAdd(&g_cnt[nrow1], 1); cl1[p] = col; }
        if (acc[nb][3] > thr1) { int p = atomicAdd(&g_cnt[nrow1], 1); cl1[p] = col + 1; }
    }
}

// ---------------------------------------------------------------------------
// Solve: exact fp32 dots, Michelot (tau0=-1), COALESCED scatter into g_outt
// ---------------------------------------------------------------------------
__global__ __launch_bounds__(256) void solve_scatter_kernel()
{
    __shared__ int   s_idx[CAP];
    __shared__ float s_val[CAP];
    __shared__ float s_rf[8];
    __shared__ int   s_ri[8];
    __shared__ float s_Mex;
    __shared__ int   s_pk;
    __shared__ int   s_pidx[1024];
    __shared__ float s_pv[1024];

    const int n    = blockIdx.x;
    const int b    = blockIdx.y;
    const int t    = threadIdx.x;
    const int wid  = t >> 5;
    const int lane = t & 31;
    const int bN   = b * NPIX;

    const int c = g_cnt[bN + n];
    if (t == 0) s_pk = 0;
    {
        const int* cl = g_cidx + ((size_t)(bN + n) << 12);
        for (int j = t; j < c; j += 256) s_idx[j] = cl[j];
    }
    __syncthreads();

    // exact fp32 dots (warp per candidate)
    {
        const float2 en = *(const float2*)&g_et[(size_t)(bN + n) * CR + lane * 2];
        for (int j = wid; j < c; j += 8) {
            int mcol = s_idx[j];
            float2 em = *(const float2*)&g_et[(size_t)(bN + mcol) * CR + lane * 2];
            float sum = en.x * em.x + en.y * em.y;
            #pragma unroll
            for (int o = 16; o; o >>= 1) sum += __shfl_xor_sync(0xffffffffu, sum, o);
            if (lane == 0) s_val[j] = sum;
        }
    }
    __syncthreads();

    // exact max over candidates
    {
        float mm = -3.0e38f;
        for (int j = t; j < c; j += 256) mm = fmaxf(mm, s_val[j]);
        #pragma unroll
        for (int o = 16; o; o >>= 1) mm = fmaxf(mm, __shfl_xor_sync(0xffffffffu, mm, o));
        if (lane == 0) s_rf[wid] = mm;
        __syncthreads();
        if (t == 0) {
            float v = s_rf[0];
            #pragma unroll
            for (int w = 1; w < 8; w++) v = fmaxf(v, s_rf[w]);
            s_Mex = v;
        }
        __syncthreads();
    }
    const float Mex = s_Mex;

    // Michelot from tau0 = -1
    float tau = -1.0f;
    int prev = -1;
    for (int it = 0; it < 32; it++) {
        float ss = 0.f; int cnt = 0;
        for (int j = t; j < c; j += 256) {
            float z = s_val[j] - Mex;
            if (z > tau) { ss += z; cnt++; }
        }
        #pragma unroll
        for (int o = 16; o; o >>= 1) {
            ss  += __shfl_xor_sync(0xffffffffu, ss, o);
            cnt += __shfl_xor_sync(0xffffffffu, cnt, o);
        }
        if (lane == 0) { s_rf[wid] = ss; s_ri[wid] = cnt; }
        __syncthreads();
        float tss = 0.f; int tcn = 0;
        #pragma unroll
        for (int w = 0; w < 8; w++) { tss += s_rf[w]; tcn += s_ri[w]; }
        __syncthreads();
        tau = (tss - 1.f) / (float)tcn;
        if (tcn == prev) break;
        prev = tcn;
    }

    // positive-support compaction
    const unsigned lt_mask = (1u << lane) - 1u;
    for (int j0 = 0; j0 < c; j0 += 256) {
        int j = j0 + t;
        float p = 0.f;
        bool pos = false;
        if (j < c) {
            p = s_val[j] - Mex - tau;
            pos = p > 0.f;
        }
        unsigned mk = __ballot_sync(0xffffffffu, pos);
        int base = 0;
        if (lane == 0 && mk) base = atomicAdd(&s_pk, __popc(mk));
        base = __shfl_sync(0xffffffffu, base, 0);
        if (pos) {
            int pi = base + __popc(mk & lt_mask);
            if (pi < 1024) { s_pidx[pi] = s_idx[j]; s_pv[pi] = p; }
        }
    }
    __syncthreads();

    // coalesced scatter: outt[m][c] += p * xt[n][c]
    const float xv = g_xt[(size_t)(bN + n) * CIN + t];
    float* ot = g_outt + (size_t)bN * CIN;
    if (s_pk <= 1024) {
        const int kp = s_pk;
        for (int jj = 0; jj < kp; jj++)
            atomicAdd(&ot[(size_t)s_pidx[jj] * CIN + t], s_pv[jj] * xv);
    } else {
        for (int j = 0; j < c; j++) {
            float p = s_val[j] - Mex - tau;
            if (p > 0.f)
                atomicAdd(&ot[(size_t)s_idx[j] * CIN + t], p * xv);
        }
    }
}

// ---------------------------------------------------------------------------
// out[b][c][n] = x[b][c][n] + outt[b][n][c]   (transpose + add)
// ---------------------------------------------------------------------------
__global__ __launch_bounds__(256) void final_add_kernel(
    const float* __restrict__ x, float* __restrict__ out)
{
    __shared__ float s[32][33];
    const int b  = blockIdx.z;
    const int n0 = blockIdx.x * 32;
    const int c0 = blockIdx.y * 32;
    const int tx = threadIdx.x, ty = threadIdx.y;
    #pragma unroll
    for (int j = 0; j < 4; j++) {
        int n = n0 + ty + j * 8;
        s[ty + j * 8][tx] = g_outt[((size_t)(b * NPIX) + n) * CIN + c0 + tx];
    }
    __syncthreads();
    #pragma unroll
    for (int j = 0; j < 4; j++) {
        int c = c0 + ty + j * 8;
        size_t o = (size_t)(b * CIN + c) * NPIX + n0 + tx;
        out[o] = x[o] + s[tx][ty + j * 8];
    }
}

// ---------------------------------------------------------------------------
extern "C" void kernel_launch(void* const* d_in, const int* in_sizes, int n_in,
                              void* d_out, int out_size)
{
    const float* x      = (const float*)d_in[0];
    const float* conv_w = (const float*)d_in[1];
    const float* conv_b = (const float*)d_in[2];
    const float* gamma  = (const float*)d_in[3];
    const float* beta   = (const float*)d_in[4];
    const float* mean   = (const float*)d_in[5];
    const float* var    = (const float*)d_in[6];
    const float* prelu  = (const float*)d_in[7];
    float* out = (float*)d_out;

    wt_zero_kernel<<<2048, 256>>>(conv_w);

    init_transpose_kernel<<<dim3(NPIX / 32, CIN / 32, BATCH), dim3(32, 8)>>>(x);

    conv_partial_kernel<<<dim3(HH, 4, BATCH), 256>>>(x);

    conv_epilogue_kernel<<<dim3(NPIX / 32, BATCH), 256>>>(
        conv_b, gamma, beta, mean, var, prelu);

    gemm_filter_mma_kernel<<<dim3(NPIX / 256, NPIX / 64, BATCH), 256>>>();

    solve_scatter_kernel<<<dim3(NPIX, BATCH), 256>>>();

    final_add_kernel<<<dim3(NPIX / 32, CIN / 32, BATCH), dim3(32, 8)>>>(x, out);
}